// round 10
// baseline (speedup 1.0000x reference)
#include <cuda_runtime.h>
#include <cuda_fp16.h>
#include <cstdint>

// Fused MoE router gate — ambiguity-gated hybrid (R7-validated math, widened):
//   phase 1: fp16x3 split tensor-core GEMM (512 thr, 4m x 4n warps)
//   phase 2: approx top-9 gap gate -> emit, or queue + bit-exact R1-replica.

#define MT  128
#define NE  64
#define KC  32
#define TPB 512
#define PADE 40
#define NCAND 9
#define TAU 2e-4f

#define SCALE_A 256.0f
#define SCALE_B 1024.0f
#define INV_SCALE (1.0f / (SCALE_A * SCALE_B))   // 2^-18

#define LG_STRIDE (NE + 1)
#define WPOOL_F   8352
#define WARPW_F   528              // per-warp: Wa[8][33] + Wb[8][33]
#define QUEUE_F   16800
#define SMEM_BYTES 69632

__device__ __half g_Wh[NE * 2048];
__device__ __half g_Wl[NE * 2048];

struct GemmS {
    __half Ah[2][MT][PADE];
    __half Al[2][MT][PADE];
    __half Bh[2][NE][PADE];
    __half Bl[2][NE][PADE];
};

__device__ __forceinline__ uint32_t sptr(const void* p) {
    return (uint32_t)__cvta_generic_to_shared(p);
}

#define LDSM4(r0, r1, r2, r3, addr)                                          \
    asm volatile("ldmatrix.sync.aligned.m8n8.x4.shared.b16 {%0,%1,%2,%3}, [%4];" \
                 : "=r"(r0), "=r"(r1), "=r"(r2), "=r"(r3) : "r"(addr))

#define MMA16816(C, a0, a1, a2, a3, b0, b1)                                  \
    asm volatile("mma.sync.aligned.m16n8k16.row.col.f32.f16.f16.f32 "        \
                 "{%0,%1,%2,%3}, {%4,%5,%6,%7}, {%8,%9}, {%0,%1,%2,%3};"     \
                 : "+f"((C)[0]), "+f"((C)[1]), "+f"((C)[2]), "+f"((C)[3])    \
                 : "r"(a0), "r"(a1), "r"(a2), "r"(a3), "r"(b0), "r"(b1))

__device__ __forceinline__ void split4(float4 v, float sc, uint2& hi, uint2& lo) {
    const float x0 = v.x * sc, x1 = v.y * sc, x2 = v.z * sc, x3 = v.w * sc;
    const __half h0 = __float2half_rn(x0);
    const __half h1 = __float2half_rn(x1);
    const __half h2 = __float2half_rn(x2);
    const __half h3 = __float2half_rn(x3);
    const __half l0 = __float2half_rn(x0 - __half2float(h0));
    const __half l1 = __float2half_rn(x1 - __half2float(h1));
    const __half l2 = __float2half_rn(x2 - __half2float(h2));
    const __half l3 = __float2half_rn(x3 - __half2float(h3));
    __half2 ph01{h0, h1}, ph23{h2, h3}, pl01{l0, l1}, pl23{l2, l3};
    hi.x = *(uint32_t*)&ph01; hi.y = *(uint32_t*)&ph23;
    lo.x = *(uint32_t*)&pl01; lo.y = *(uint32_t*)&pl23;
}

// prep: split W*SCALE_B into fp16 hi/lo once (identical formula to in-loop split)
__global__ void split_w_kernel(const float* __restrict__ W, int n4)
{
    const int i = blockIdx.x * blockDim.x + threadIdx.x;
    if (i < n4) {
        uint2 hi, lo;
        split4(((const float4*)W)[i], SCALE_B, hi, lo);
        *(uint2*)&g_Wh[i * 4] = hi;
        *(uint2*)&g_Wl[i * 4] = lo;
    }
}

__global__ __launch_bounds__(TPB)
void router_hybrid(const float* __restrict__ H,
                   const float* __restrict__ W,
                   const float* __restrict__ cal_scale,
                   const float* __restrict__ cal_bias,
                   float* __restrict__ out_probs,
                   float* __restrict__ out_w,
                   float* __restrict__ out_idx,
                   int T, int D)
{
    extern __shared__ float smemf[];
    GemmS* gs = (GemmS*)smemf;
    float* Lg = smemf;
    float* wpool = smemf + WPOOL_F;
    int*   queue = (int*)(smemf + QUEUE_F);
    int*   qcount = queue + MT;

    const int tid  = threadIdx.x;
    const int lane = tid & 31;
    const int warp = tid >> 5;               // 0..15
    const int wm   = warp >> 2;              // 0..3 : m32 stripe
    const int wn   = warp & 3;               // 0..3 : n16 stripe
    const int m_base = blockIdx.x * MT;

    if (tid == 0) *qcount = 0;

    // ================= phase 1: fp16x3 MMA GEMM =================
    const int arow = tid >> 2;               // 0..127
    const int acb  = (tid & 3) * 8;          // 0,8,16,24
    const int brow = tid >> 3;               // 0..63
    const int bcb  = (tid & 7) * 4;          // 0..28 step 4 (halves)

    const bool a_ok = (m_base + arow) < T;
    const float*  Ap  = H + (size_t)(m_base + arow) * D + acb;
    const __half* Bph = g_Wh + (size_t)brow * D + bcb;
    const __half* Bpl = g_Wl + (size_t)brow * D + bcb;

    const float4 z4 = make_float4(0.f, 0.f, 0.f, 0.f);
    float4 areg[2];
    uint2  bregh, bregl;
    #pragma unroll
    for (int j = 0; j < 2; ++j) areg[j] = a_ok ? *(const float4*)(Ap + j * 4) : z4;
    bregh = *(const uint2*)Bph;
    bregl = *(const uint2*)Bpl;

    float accM[16], accS[16];
    #pragma unroll
    for (int i = 0; i < 16; ++i) { accM[i] = 0.f; accS[i] = 0.f; }

    const int a_r = wm * 32 + (lane & 15);
    const int a_c = (lane >> 4) << 3;
    const int b_r = wn * 16 + ((lane >> 4) << 3) + (lane & 7);
    const int b_c = ((lane >> 3) & 1) << 3;

    const int KT = D / KC;
    int buf = 0;
    for (int kt = 0; kt < KT; ++kt) {
        #pragma unroll
        for (int j = 0; j < 2; ++j) {
            uint2 hi, lo;
            split4(areg[j], SCALE_A, hi, lo);
            *(uint2*)&gs->Ah[buf][arow][acb + j * 4] = hi;
            *(uint2*)&gs->Al[buf][arow][acb + j * 4] = lo;
        }
        *(uint2*)&gs->Bh[buf][brow][bcb] = bregh;
        *(uint2*)&gs->Bl[buf][brow][bcb] = bregl;
        __syncthreads();

        if (kt + 1 < KT) {
            const float* Apn = Ap + (size_t)(kt + 1) * KC;
            #pragma unroll
            for (int j = 0; j < 2; ++j) areg[j] = a_ok ? *(const float4*)(Apn + j * 4) : z4;
            bregh = *(const uint2*)(Bph + (size_t)(kt + 1) * KC);
            bregl = *(const uint2*)(Bpl + (size_t)(kt + 1) * KC);
        }

        #pragma unroll
        for (int ks = 0; ks < 2; ++ks) {
            const int k16 = ks * 16;
            uint32_t ah[8], al[8], bh[4], bl[4];
            #pragma unroll
            for (int mi = 0; mi < 2; ++mi) {
                uint32_t adr = sptr(&gs->Ah[buf][a_r + mi * 16][k16 + a_c]);
                LDSM4(ah[mi*4+0], ah[mi*4+1], ah[mi*4+2], ah[mi*4+3], adr);
                adr = sptr(&gs->Al[buf][a_r + mi * 16][k16 + a_c]);
                LDSM4(al[mi*4+0], al[mi*4+1], al[mi*4+2], al[mi*4+3], adr);
            }
            {
                uint32_t adr = sptr(&gs->Bh[buf][b_r][k16 + b_c]);
                LDSM4(bh[0], bh[1], bh[2], bh[3], adr);
                adr = sptr(&gs->Bl[buf][b_r][k16 + b_c]);
                LDSM4(bl[0], bl[1], bl[2], bl[3], adr);
            }
            #pragma unroll
            for (int mi = 0; mi < 2; ++mi) {
                #pragma unroll
                for (int ni = 0; ni < 2; ++ni) {
                    float* CM = accM + (mi * 2 + ni) * 4;
                    float* CS = accS + (mi * 2 + ni) * 4;
                    MMA16816(CM, ah[mi*4+0], ah[mi*4+1], ah[mi*4+2], ah[mi*4+3],
                             bh[ni*2], bh[ni*2+1]);
                    MMA16816(CS, ah[mi*4+0], ah[mi*4+1], ah[mi*4+2], ah[mi*4+3],
                             bl[ni*2], bl[ni*2+1]);
                    MMA16816(CS, al[mi*4+0], al[mi*4+1], al[mi*4+2], al[mi*4+3],
                             bh[ni*2], bh[ni*2+1]);
                }
            }
        }
        buf ^= 1;
    }

    // ---------- calibrate -> Lg ----------
    __syncthreads();
    #pragma unroll
    for (int mi = 0; mi < 2; ++mi) {
        #pragma unroll
        for (int ni = 0; ni < 2; ++ni) {
            const float* CM = accM + (mi * 2 + ni) * 4;
            const float* CS = accS + (mi * 2 + ni) * 4;
            const int r0 = wm * 32 + mi * 16 + (lane >> 2);
            const int n0 = wn * 16 + ni * 8 + 2 * (lane & 3);
            const float s0 = __ldg(cal_scale + n0) * INV_SCALE;
            const float s1 = __ldg(cal_scale + n0 + 1) * INV_SCALE;
            const float bb0 = __ldg(cal_bias + n0), bb1 = __ldg(cal_bias + n0 + 1);
            Lg[(r0    ) * LG_STRIDE + n0]     = (CM[0] + CS[0]) * s0 + bb0;
            Lg[(r0    ) * LG_STRIDE + n0 + 1] = (CM[1] + CS[1]) * s1 + bb1;
            Lg[(r0 + 8) * LG_STRIDE + n0]     = (CM[2] + CS[2]) * s0 + bb0;
            Lg[(r0 + 8) * LG_STRIDE + n0 + 1] = (CM[3] + CS[3]) * s1 + bb1;
        }
    }
    __syncthreads();

    // ============ phase 2: softmax + gated top-8 ============
    for (int t = warp; t < MT; t += (TPB / 32)) {
        const int tg = m_base + t;
        if (tg >= T) break;

        const float v0 = Lg[t * LG_STRIDE + lane];
        const float v1 = Lg[t * LG_STRIDE + lane + 32];

        float mx = fmaxf(v0, v1);
        #pragma unroll
        for (int o = 16; o; o >>= 1)
            mx = fmaxf(mx, __shfl_xor_sync(0xffffffffu, mx, o));

        const float e0 = expf(v0 - mx);
        const float e1 = expf(v1 - mx);
        float s = e0 + e1;
        #pragma unroll
        for (int o = 16; o; o >>= 1)
            s += __shfl_xor_sync(0xffffffffu, s, o);

        const float inv = 1.0f / s;
        const float q0 = e0 * inv;
        const float q1 = e1 * inv;

        out_probs[(size_t)tg * NE + lane]      = q0;
        out_probs[(size_t)tg * NE + lane + 32] = q1;

        float p0 = q0, p1 = q1;
        float bvs[NCAND]; int cds[NCAND];
        #pragma unroll
        for (int r = 0; r < NCAND; ++r) {
            float bv; int bi;
            if (p0 >= p1) { bv = p0; bi = lane; }
            else          { bv = p1; bi = lane + 32; }
            #pragma unroll
            for (int o = 16; o; o >>= 1) {
                const float ov = __shfl_xor_sync(0xffffffffu, bv, o);
                const int   oi = __shfl_xor_sync(0xffffffffu, bi, o);
                if (ov > bv || (ov == bv && oi < bi)) { bv = ov; bi = oi; }
            }
            bvs[r] = bv; cds[r] = bi;
            if (bi == lane)           p0 = -1.0f;
            else if (bi == lane + 32) p1 = -1.0f;
        }

        bool amb = false;
        #pragma unroll
        for (int r = 0; r < 8; ++r)
            amb = amb || ((bvs[r] - bvs[r + 1]) < bvs[r] * TAU);

        if (!amb) {
            if (lane == 0) {
                #pragma unroll
                for (int r = 0; r < 8; ++r) {
                    out_w[(size_t)tg * 8 + r]   = bvs[r];
                    out_idx[(size_t)tg * 8 + r] = (float)cds[r];
                }
            }
        } else if (lane == 0) {
            const int q = atomicAdd(qcount, 1);
            queue[q] = tg;
        }
    }
    __syncthreads();

    // ====== replica pass: bit-exact R1 arithmetic on queued tokens ======
    const int nq = *qcount;
    float* Wa = wpool + warp * WARPW_F;      // [8][33]
    float* Wb = Wa + 264;                    // [8][33]
    const int erow = lane >> 1;              // 0..15
    const int slot = lane & 1;               // 0..1
    const int D4 = D / 4;

    for (int qi = warp; qi < nq; qi += (TPB / 32)) {
        const int tg = queue[qi];
        const float4* H4 = (const float4*)(H + (size_t)tg * D);
        const float4* W4 = (const float4*)W;

        float acc0 = 0.f, acc1 = 0.f;
        float4 pre[4];
        #pragma unroll
        for (int j = 0; j < 4; ++j)
            pre[j] = W4[(size_t)(erow + 16 * j) * D4 + slot];

        for (int kb = 0; kb < 256; ++kb) {   // 8 k per block, k ascending
            #pragma unroll
            for (int j = 0; j < 4; ++j) {
                const int e = erow + 16 * j;
                float* dst = (e < 32) ? (Wa + e) : (Wb + (e - 32));
                const int base = slot * 4;
                dst[(base + 0) * 33] = pre[j].x;
                dst[(base + 1) * 33] = pre[j].y;
                dst[(base + 2) * 33] = pre[j].z;
                dst[(base + 3) * 33] = pre[j].w;
            }
            __syncwarp();
            if (kb + 1 < 256) {
                #pragma unroll
                for (int j = 0; j < 4; ++j)
                    pre[j] = W4[(size_t)(erow + 16 * j) * D4 + (kb + 1) * 2 + slot];
            }
            #pragma unroll
            for (int q4 = 0; q4 < 2; ++q4) {
                const float4 h = H4[kb * 2 + q4];
                const int k0 = q4 * 4;
                acc0 = fmaf(h.x, Wa[(k0 + 0) * 33 + lane], acc0);
                acc0 = fmaf(h.y, Wa[(k0 + 1) * 33 + lane], acc0);
                acc0 = fmaf(h.z, Wa[(k0 + 2) * 33 + lane], acc0);
                acc0 = fmaf(h.w, Wa[(k0 + 3) * 33 + lane], acc0);
                acc1 = fmaf(h.x, Wb[(k0 + 0) * 33 + lane], acc1);
                acc1 = fmaf(h.y, Wb[(k0 + 1) * 33 + lane], acc1);
                acc1 = fmaf(h.z, Wb[(k0 + 2) * 33 + lane], acc1);
                acc1 = fmaf(h.w, Wb[(k0 + 3) * 33 + lane], acc1);
            }
            __syncwarp();
        }

        const float sc0 = cal_scale[lane];
        const float sc1 = cal_scale[lane + 32];
        const float cb0 = cal_bias[lane];
        const float cb1 = cal_bias[lane + 32];
        const float v0 = acc0 * sc0 + cb0;
        const float v1 = acc1 * sc1 + cb1;

        float mx = fmaxf(v0, v1);
        #pragma unroll
        for (int o = 16; o; o >>= 1)
            mx = fmaxf(mx, __shfl_xor_sync(0xffffffffu, mx, o));

        const float e0 = expf(v0 - mx);
        const float e1 = expf(v1 - mx);
        float s = e0 + e1;
        #pragma unroll
        for (int o = 16; o; o >>= 1)
            s += __shfl_xor_sync(0xffffffffu, s, o);

        const float inv = 1.0f / s;
        float p0 = e0 * inv;
        float p1 = e1 * inv;

        #pragma unroll
        for (int r = 0; r < 8; ++r) {
            float bv; int bi;
            if (p0 >= p1) { bv = p0; bi = lane; }
            else          { bv = p1; bi = lane + 32; }
            #pragma unroll
            for (int o = 16; o; o >>= 1) {
                const float ov = __shfl_xor_sync(0xffffffffu, bv, o);
                const int   oi = __shfl_xor_sync(0xffffffffu, bi, o);
                if (ov > bv || (ov == bv && oi < bi)) { bv = ov; bi = oi; }
            }
            if (lane == 0) {
                out_w[(size_t)tg * 8 + r]   = bv;
                out_idx[(size_t)tg * 8 + r] = (float)bi;
            }
            if (bi == lane)           p0 = -1.0f;
            else if (bi == lane + 32) p1 = -1.0f;
        }
    }
}

extern "C" void kernel_launch(void* const* d_in, const int* in_sizes, int n_in,
                              void* d_out, int out_size)
{
    const float* H  = (const float*)d_in[0];
    const float* W  = (const float*)d_in[1];
    const float* cs = (const float*)d_in[2];
    const float* cb = (const float*)d_in[3];

    const int E = in_sizes[2];
    const int D = in_sizes[1] / E;
    const int T = in_sizes[0] / D;

    float* out       = (float*)d_out;
    float* out_probs = out;
    float* out_w     = out + (size_t)T * E;
    float* out_idx   = out_w + (size_t)T * 8;

    const int n4 = (E * D) / 4;
    split_w_kernel<<<(n4 + 255) / 256, 256>>>(W, n4);

    cudaFuncSetAttribute(router_hybrid,
                         cudaFuncAttributeMaxDynamicSharedMemorySize,
                         SMEM_BYTES);

    const int grid = (T + MT - 1) / MT;
    router_hybrid<<<grid, TPB, SMEM_BYTES>>>(H, W, cs, cb,
                                             out_probs, out_w, out_idx, T, D);
}

// round 11
// speedup vs baseline: 1.1257x; 1.1257x over previous
#include <cuda_runtime.h>
#include <cuda_bf16.h>

// Fused MoE router gate — pure fp32 FFMA (R1 math, rebalanced blocking):
//   logits = (H[T,D] @ W[E,D]^T) * cal_scale + cal_bias
//   probs  -> out[0:T*E]; top8 weights -> out[T*E:+T*8]; top8 idx -> +T*8
// 8x4 register blocking: 3 LDS.128 per 32 FMA (FMA-bound, crossbar 25% slack).
// Every output element = sequential k-ascending FFMA chain, operand-identical
// to the R1 kernel that passed (rel_err 1.08e-7, indices exact).

#define KC  16      // K chunk per stage
#define MT  32      // token tile per block
#define NE  64      // experts
#define TPB 64      // 2 warps; 16 tx * 4 ty; thread tile 8 (m) x 4 (n)

__global__ __launch_bounds__(TPB)
void router_ffma(const float* __restrict__ H,
                 const float* __restrict__ W,
                 const float* __restrict__ cal_scale,
                 const float* __restrict__ cal_bias,
                 float* __restrict__ out_probs,
                 float* __restrict__ out_w,
                 float* __restrict__ out_idx,
                 int T, int D)
{
    __shared__ __align__(16) union {
        struct {
            float As[2][KC][MT + 4];   // [k][m] transposed
            float Bs[2][KC][NE + 4];   // [k][e] transposed
        } s;
        float Lg[MT][NE + 1];
    } sm;

    const int tid = threadIdx.x;
    const int tx  = tid & 15;          // n0 = tx*4
    const int ty  = tid >> 4;          // m0 = ty*8  (0..3)
    const int m_base = blockIdx.x * MT;

    // ---- loaders ----
    const int lrow = tid >> 1;         // 0..31 token row (A)
    const int lk   = (tid & 1) * 8;    // k offset 0/8    (A)
    const int brow = tid;              // 0..63 expert row (B)

    const bool a_ok = (m_base + lrow) < T;
    const float* Ap = H + (size_t)(m_base + lrow) * D + lk;
    const float* Bp = W + (size_t)brow * D;

    const float4 z4 = make_float4(0.f, 0.f, 0.f, 0.f);
    float4 a_pf[2], b_pf[4];
    #pragma unroll
    for (int j = 0; j < 2; ++j) a_pf[j] = a_ok ? *(const float4*)(Ap + j * 4) : z4;
    #pragma unroll
    for (int j = 0; j < 4; ++j) b_pf[j] = *(const float4*)(Bp + j * 4);

    float acc[8][4];
    #pragma unroll
    for (int i = 0; i < 8; ++i)
        #pragma unroll
        for (int j = 0; j < 4; ++j) acc[i][j] = 0.f;

    const int KT = D / KC;             // 128 stages
    int buf = 0;
    for (int kt = 0; kt < KT; ++kt) {
        // store prefetched stage (transposed)
        #pragma unroll
        for (int j = 0; j < 2; ++j) {
            sm.s.As[buf][lk + j * 4 + 0][lrow] = a_pf[j].x;
            sm.s.As[buf][lk + j * 4 + 1][lrow] = a_pf[j].y;
            sm.s.As[buf][lk + j * 4 + 2][lrow] = a_pf[j].z;
            sm.s.As[buf][lk + j * 4 + 3][lrow] = a_pf[j].w;
        }
        #pragma unroll
        for (int j = 0; j < 4; ++j) {
            sm.s.Bs[buf][j * 4 + 0][brow] = b_pf[j].x;
            sm.s.Bs[buf][j * 4 + 1][brow] = b_pf[j].y;
            sm.s.Bs[buf][j * 4 + 2][brow] = b_pf[j].z;
            sm.s.Bs[buf][j * 4 + 3][brow] = b_pf[j].w;
        }
        __syncthreads();

        // prefetch next stage
        if (kt + 1 < KT) {
            const float* Apn = Ap + (size_t)(kt + 1) * KC;
            const float* Bpn = Bp + (size_t)(kt + 1) * KC;
            #pragma unroll
            for (int j = 0; j < 2; ++j) a_pf[j] = a_ok ? *(const float4*)(Apn + j * 4) : z4;
            #pragma unroll
            for (int j = 0; j < 4; ++j) b_pf[j] = *(const float4*)(Bpn + j * 4);
        }

        // rank-1 updates: 8x4 per thread per k
        #pragma unroll
        for (int k = 0; k < KC; ++k) {
            const float4 av0 = *(const float4*)&sm.s.As[buf][k][ty * 8];
            const float4 av1 = *(const float4*)&sm.s.As[buf][k][ty * 8 + 4];
            const float4 bv  = *(const float4*)&sm.s.Bs[buf][k][tx * 4];
            const float a[8] = {av0.x, av0.y, av0.z, av0.w,
                                av1.x, av1.y, av1.z, av1.w};
            const float b0 = bv.x, b1 = bv.y, b2 = bv.z, b3 = bv.w;
            #pragma unroll
            for (int i = 0; i < 8; ++i) {
                acc[i][0] = fmaf(a[i], b0, acc[i][0]);
                acc[i][1] = fmaf(a[i], b1, acc[i][1]);
                acc[i][2] = fmaf(a[i], b2, acc[i][2]);
                acc[i][3] = fmaf(a[i], b3, acc[i][3]);
            }
        }
        buf ^= 1;
    }

    // ---- calibrate -> Lg (smem union; sync before reuse) ----
    __syncthreads();
    #pragma unroll
    for (int j = 0; j < 4; ++j) {
        const int n = tx * 4 + j;
        const float s = cal_scale[n];
        const float b = cal_bias[n];
        #pragma unroll
        for (int i = 0; i < 8; ++i)
            sm.Lg[ty * 8 + i][n] = acc[i][j] * s + b;
    }
    __syncthreads();

    // ---- warp-per-token softmax + top-8 (R1 verbatim) ----
    const int warp = tid >> 5;
    const int lane = tid & 31;
    for (int t = warp; t < MT; t += (TPB / 32)) {
        const int tg = m_base + t;
        if (tg >= T) break;

        float v0 = sm.Lg[t][lane];
        float v1 = sm.Lg[t][lane + 32];

        float mx = fmaxf(v0, v1);
        #pragma unroll
        for (int o = 16; o; o >>= 1)
            mx = fmaxf(mx, __shfl_xor_sync(0xffffffffu, mx, o));

        float e0 = expf(v0 - mx);
        float e1 = expf(v1 - mx);
        float s = e0 + e1;
        #pragma unroll
        for (int o = 16; o; o >>= 1)
            s += __shfl_xor_sync(0xffffffffu, s, o);

        const float inv = 1.0f / s;
        float p0 = e0 * inv;
        float p1 = e1 * inv;

        out_probs[(size_t)tg * NE + lane]      = p0;
        out_probs[(size_t)tg * NE + lane + 32] = p1;

        #pragma unroll
        for (int r = 0; r < 8; ++r) {
            float bv; int bi;
            if (p0 >= p1) { bv = p0; bi = lane; }
            else          { bv = p1; bi = lane + 32; }
            #pragma unroll
            for (int o = 16; o; o >>= 1) {
                const float ov = __shfl_xor_sync(0xffffffffu, bv, o);
                const int   oi = __shfl_xor_sync(0xffffffffu, bi, o);
                if (ov > bv || (ov == bv && oi < bi)) { bv = ov; bi = oi; }
            }
            if (lane == 0) {
                out_w[(size_t)tg * 8 + r]   = bv;
                out_idx[(size_t)tg * 8 + r] = (float)bi;
            }
            if (bi == lane)           p0 = -1.0f;
            else if (bi == lane + 32) p1 = -1.0f;
        }
    }
}

extern "C" void kernel_launch(void* const* d_in, const int* in_sizes, int n_in,
                              void* d_out, int out_size)
{
    const float* H  = (const float*)d_in[0];   // hidden_states [B,S,D] fp32
    const float* W  = (const float*)d_in[1];   // router_weight [E,D]  fp32
    const float* cs = (const float*)d_in[2];   // cal_scale [E]
    const float* cb = (const float*)d_in[3];   // cal_bias  [E]

    const int E = in_sizes[2];                 // 64
    const int D = in_sizes[1] / E;             // 2048
    const int T = in_sizes[0] / D;             // 16384

    float* out       = (float*)d_out;
    float* out_probs = out;                    // [T, E]
    float* out_w     = out + (size_t)T * E;    // [T, 8]
    float* out_idx   = out_w + (size_t)T * 8;  // [T, 8]

    const int grid = (T + MT - 1) / MT;        // 512
    router_ffma<<<grid, TPB>>>(H, W, cs, cb, out_probs, out_w, out_idx, T, D);
}